// round 14
// baseline (speedup 1.0000x reference)
#include <cuda_runtime.h>
#include <cuda_bf16.h>
#include <math.h>
#include <stdint.h>

// ---------------------------------------------------------------------------
// Arch gate: tcgen05/TMEM are sm_103a-SPECIFIC. The harness build also emits
// a generic compute_103 PTX stage, which must not see tcgen05 instructions.
// ---------------------------------------------------------------------------
#if defined(__CUDA_ARCH__) && \
    (defined(__CUDA_ARCH_FEAT_SM103_ALL) || defined(__CUDA_ARCH_FEAT_SM100_ALL) || \
     defined(__CUDA_ARCH_SPECIFIC__))
#define HAS_TCGEN05 1
#else
#define HAS_TCGEN05 0
#endif

// ---------------------------------------------------------------------------
// Problem constants
// ---------------------------------------------------------------------------
#define T_TOK   4096
#define D_IN    1024
#define H_DIM   4096
#define E_EXP   8
#define R_RANK  32
#define SCALING 0.03125f
#define MAX_TILES 40

// ---------------------------------------------------------------------------
// Device scratch
// ---------------------------------------------------------------------------
__device__ int   g_idx[T_TOK];
__device__ int   g_perm[T_TOK];
__device__ int   g_tile_expert[MAX_TILES];
__device__ int   g_tile_start[MAX_TILES];
__device__ int   g_tile_rows[MAX_TILES];
__device__ float g_h[T_TOK * R_RANK];
__device__ float g_abuf[(size_t)T_TOK * H_DIM];      // gelu(down) fp32 (LoRA input)
__device__ float g_lora[(size_t)T_TOK * H_DIM];      // lora + bias staging
// hi/lo bf16 split planes
__device__ __nv_bfloat16 g_xhi[(size_t)T_TOK * D_IN];
__device__ __nv_bfloat16 g_xlo[(size_t)T_TOK * D_IN];
__device__ __nv_bfloat16 g_w1hi[(size_t)H_DIM * D_IN];
__device__ __nv_bfloat16 g_w1lo[(size_t)H_DIM * D_IN];
__device__ __nv_bfloat16 g_w2hi[(size_t)D_IN * H_DIM];
__device__ __nv_bfloat16 g_w2lo[(size_t)D_IN * H_DIM];
__device__ __nv_bfloat16 g_ahi[(size_t)T_TOK * H_DIM];
__device__ __nv_bfloat16 g_alo[(size_t)T_TOK * H_DIM];

// ---------------------------------------------------------------------------
// PTX helpers
// ---------------------------------------------------------------------------
__device__ __forceinline__ uint32_t elect_one_pred() {
    uint32_t pred;
    asm volatile(
        "{\n\t.reg .pred p;\n\t"
        "elect.sync _|p, 0xFFFFFFFF;\n\t"
        "selp.b32 %0, 1, 0, p;\n\t}"
        : "=r"(pred));
    return pred;
}
__device__ __forceinline__ uint32_t smem_to_u32(const void* p) {
    uint32_t a;
    asm("{ .reg .u64 t; cvta.to.shared.u64 t, %1; cvt.u32.u64 %0, t; }"
        : "=r"(a) : "l"(p));
    return a;
}
#define MBARRIER_INIT(addr, cnt) \
    asm volatile("mbarrier.init.shared.b64 [%0], %1;" :: "r"((uint32_t)(addr)), "r"((uint32_t)(cnt)) : "memory")
#define MBARRIER_WAIT_PARITY(mbar_smem_addr, phase_parity) do { \
    uint32_t _mbar = (uint32_t)(mbar_smem_addr); \
    uint32_t _parity = (uint32_t)(phase_parity); \
    uint32_t _done; \
    asm volatile( \
        "{\n\t.reg .pred p;\n\t" \
        "mbarrier.try_wait.parity.acquire.cta.shared::cta.b64 p, [%1], %2;\n\t" \
        "selp.b32 %0, 1, 0, p;\n\t}" \
        : "=r"(_done) : "r"(_mbar), "r"(_parity) : "memory"); \
    if (!_done) { \
        asm volatile( \
            "{\n\t.reg .pred P1;\n\t" \
            "WAIT_LOOP_%=:\n\t" \
            "mbarrier.try_wait.parity.acquire.cta.shared::cta.b64 P1, [%0], %1, 0x989680;\n\t" \
            "@P1 bra.uni WAIT_DONE_%=;\n\t" \
            "bra.uni WAIT_LOOP_%=;\n\t" \
            "WAIT_DONE_%=:\n\t}" \
            :: "r"(_mbar), "r"(_parity) : "memory"); \
    } \
} while(0)
#define FENCE_PROXY_ASYNC()    asm volatile("fence.proxy.async.shared::cta;" ::: "memory")

#if HAS_TCGEN05
#define TCGEN05_ALLOC(sa, n) \
    asm volatile("tcgen05.alloc.cta_group::1.sync.aligned.shared::cta.b32 [%0], %1;" \
                 :: "r"((uint32_t)(sa)), "r"((uint32_t)(n)) : "memory")
#define TCGEN05_DEALLOC(t, n) \
    asm volatile("tcgen05.dealloc.cta_group::1.sync.aligned.b32 %0, %1;" :: "r"(t), "r"(n))
#define TCGEN05_RELINQUISH() \
    asm volatile("tcgen05.relinquish_alloc_permit.cta_group::1.sync.aligned;")
#define TCGEN05_COMMIT(mb) \
    asm volatile("tcgen05.commit.cta_group::1.mbarrier::arrive::one.shared::cluster.b64 [%0];" \
                 :: "r"((uint32_t)(mb)) : "memory")
#define TCGEN05_FENCE_AFTER()  asm volatile("tcgen05.fence::after_thread_sync;" ::: "memory")
#define TCGEN05_FENCE_BEFORE() asm volatile("tcgen05.fence::before_thread_sync;" ::: "memory")
#define TCGEN05_WAIT_LD()      asm volatile("tcgen05.wait::ld.sync.aligned;" ::: "memory")
#define TCGEN05_LD_32X32B_X32(r, ta) \
    asm volatile( \
        "tcgen05.ld.sync.aligned.32x32b.x32.b32 " \
        "{%0, %1, %2, %3, %4, %5, %6, %7, " \
        " %8, %9, %10, %11, %12, %13, %14, %15, " \
        " %16, %17, %18, %19, %20, %21, %22, %23, " \
        " %24, %25, %26, %27, %28, %29, %30, %31}, [%32];" \
        : "=r"((r)[0]),  "=r"((r)[1]),  "=r"((r)[2]),  "=r"((r)[3]), \
          "=r"((r)[4]),  "=r"((r)[5]),  "=r"((r)[6]),  "=r"((r)[7]), \
          "=r"((r)[8]),  "=r"((r)[9]),  "=r"((r)[10]), "=r"((r)[11]), \
          "=r"((r)[12]), "=r"((r)[13]), "=r"((r)[14]), "=r"((r)[15]), \
          "=r"((r)[16]), "=r"((r)[17]), "=r"((r)[18]), "=r"((r)[19]), \
          "=r"((r)[20]), "=r"((r)[21]), "=r"((r)[22]), "=r"((r)[23]), \
          "=r"((r)[24]), "=r"((r)[25]), "=r"((r)[26]), "=r"((r)[27]), \
          "=r"((r)[28]), "=r"((r)[29]), "=r"((r)[30]), "=r"((r)[31]) \
        : "r"(ta))

// SW128 K-major smem descriptor (version=1, SBO=64, LBO=1)
static constexpr uint64_t SMEM_DESC_BASE_SW128 =
    (uint64_t(2) << 61) | (uint64_t(1) << 46) | (uint64_t(64) << 32) | (uint64_t(1) << 16);
#define MAKE_SMEM_DESC(a) (SMEM_DESC_BASE_SW128 | ((uint64_t)((a) >> 4) & 0x3FFF))

// idesc: kind::f16, bf16 a/b, f32 accum, M=128, N=256
// (1<<4)|(1<<7)|(1<<10)|((256/8)<<17)|((128/16)<<24)
#define MMA_IDESC 0x8400490u

__device__ __forceinline__ void mma_f16_ss(uint32_t d, uint64_t a, uint64_t b,
                                           uint32_t en)
{
    asm volatile(
        "{\n\t.reg .pred p;\n\t"
        "setp.ne.u32 p, %5, 0;\n\t"
        "tcgen05.mma.cta_group::1.kind::f16 [%0], %1, %2, %3, {%4, %4, %4, %4}, p;\n\t}"
        :: "r"(d), "l"(a), "l"(b), "r"(MMA_IDESC), "r"(0u), "r"(en)
        : "memory");
}
#endif  // HAS_TCGEN05

// ---------------------------------------------------------------------------
// Kernel 1: router
// ---------------------------------------------------------------------------
__global__ void router_kernel(const float* __restrict__ x,
                              const float* __restrict__ rw,
                              const float* __restrict__ rb,
                              float* __restrict__ routing,
                              float* __restrict__ ec)
{
    const int t = blockIdx.x;
    __shared__ float xs[D_IN];
    __shared__ float lg[E_EXP];
    const int tid = threadIdx.x;

    ((float4*)xs)[tid] = ((const float4*)(x + (size_t)t * D_IN))[tid];
    __syncthreads();

    const int w = tid >> 5, lane = tid & 31;
    const float* wrow = rw + (size_t)w * D_IN;
    float s = 0.f;
    for (int d = lane; d < D_IN; d += 32) s += xs[d] * wrow[d];
#pragma unroll
    for (int o = 16; o; o >>= 1) s += __shfl_xor_sync(0xFFFFFFFFu, s, o);
    if (lane == 0) lg[w] = s + rb[w];
    __syncthreads();

    if (tid == 0) {
        float m = lg[0]; int am = 0;
#pragma unroll
        for (int e = 1; e < E_EXP; e++) if (lg[e] > m) { m = lg[e]; am = e; }
        float ex[E_EXP]; float den = 0.f;
#pragma unroll
        for (int e = 0; e < E_EXP; e++) { ex[e] = expf(lg[e] - m); den += ex[e]; }
        const float inv = 1.f / den;
#pragma unroll
        for (int e = 0; e < E_EXP; e++) {
            const float r = ex[e] * inv;
            routing[t * E_EXP + e] = r;
            const float msk = (e == am) ? 1.f : 0.f;
            ec[t * E_EXP + e] = (msk - r) + r;
        }
        g_idx[t] = am;
    }
}

// ---------------------------------------------------------------------------
// Kernel 2: group tokens by expert
// ---------------------------------------------------------------------------
__global__ void group_kernel()
{
    __shared__ int cnt[E_EXP];
    __shared__ int base[E_EXP];
    const int tid = threadIdx.x;
    if (tid < E_EXP) cnt[tid] = 0;
    __syncthreads();
    for (int t = tid; t < T_TOK; t += 256) atomicAdd(&cnt[g_idx[t]], 1);
    __syncthreads();
    if (tid == 0) {
        int off = 0, slot = 0;
        for (int e = 0; e < E_EXP; e++) {
            base[e] = off;
            const int c = cnt[e];
            for (int s = 0; s < c; s += 128) {
                g_tile_expert[slot] = e;
                g_tile_start[slot]  = off + s;
                g_tile_rows[slot]   = min(128, c - s);
                slot++;
            }
            off += c;
        }
        for (; slot < MAX_TILES; slot++) g_tile_rows[slot] = 0;
    }
    __syncthreads();
    if (tid < E_EXP) cnt[tid] = base[tid];
    __syncthreads();
    for (int t = tid; t < T_TOK; t += 256) {
        const int e = g_idx[t];
        const int pos = atomicAdd(&cnt[e], 1);
        g_perm[pos] = t;
    }
}

// ---------------------------------------------------------------------------
// Kernel 3: zero rank-stage buffer
// ---------------------------------------------------------------------------
__global__ void zero_h_kernel()
{
    const int i = blockIdx.x * blockDim.x + threadIdx.x;
    if (i < T_TOK * R_RANK) g_h[i] = 0.f;
}

// ---------------------------------------------------------------------------
// Kernel: fp32 -> bf16 hi/lo split (vectorized x4)
// ---------------------------------------------------------------------------
__global__ void cvt_hilo_kernel(const float* __restrict__ s,
                                __nv_bfloat16* __restrict__ hi,
                                __nv_bfloat16* __restrict__ lo, int n4)
{
    const int i = blockIdx.x * blockDim.x + threadIdx.x;
    if (i >= n4) return;
    const float4 f = ((const float4*)s)[i];
    __nv_bfloat16 h[4], l[4];
    h[0] = __float2bfloat16(f.x); l[0] = __float2bfloat16(f.x - __bfloat162float(h[0]));
    h[1] = __float2bfloat16(f.y); l[1] = __float2bfloat16(f.y - __bfloat162float(h[1]));
    h[2] = __float2bfloat16(f.z); l[2] = __float2bfloat16(f.z - __bfloat162float(h[2]));
    h[3] = __float2bfloat16(f.w); l[3] = __float2bfloat16(f.w - __bfloat162float(h[3]));
    ((uint2*)hi)[i] = *(uint2*)h;
    ((uint2*)lo)[i] = *(uint2*)l;
}

// ---------------------------------------------------------------------------
// Kernel 4: grouped rank stage (k-split 64 for occupancy)
// ---------------------------------------------------------------------------
__global__ void rank_kernel(const float* __restrict__ in, int K, int kchunk,
                            const float* __restrict__ A,
                            const float* __restrict__ Ab)
{
    const int slot = blockIdx.x;
    const int rows = g_tile_rows[slot];
    if (rows == 0) return;
    const int e     = g_tile_expert[slot];
    const int start = g_tile_start[slot];
    const int k0    = blockIdx.y * kchunk;

    __shared__ float xs[32][132];
    __shared__ float as_s[32][36];
    __shared__ int   perm_s[128];

    const int tid = threadIdx.x;
    if (tid < 128) perm_s[tid] = (tid < rows) ? g_perm[start + tid] : 0;
    const int tg = tid >> 3;
    const int rg = tid & 7;
    float acc[4][4];
#pragma unroll
    for (int i = 0; i < 4; i++)
#pragma unroll
        for (int j = 0; j < 4; j++) acc[i][j] = 0.f;
    __syncthreads();

    for (int kk = k0; kk < k0 + kchunk; kk += 32) {
        __syncthreads();
#pragma unroll
        for (int q = 0; q < 4; q++) {
            const int f = q * 256 + tid;
            const int i = f >> 3, c = (f & 7) * 4;
            float4 v = make_float4(0.f, 0.f, 0.f, 0.f);
            if (i < rows) v = *(const float4*)(in + (size_t)perm_s[i] * K + kk + c);
            xs[c + 0][i] = v.x; xs[c + 1][i] = v.y;
            xs[c + 2][i] = v.z; xs[c + 3][i] = v.w;
        }
        {
            const int r = tid >> 3, c = (tid & 7) * 4;
            const float4 v = *(const float4*)(A + ((size_t)e * R_RANK + r) * K + kk + c);
            as_s[c + 0][r] = v.x; as_s[c + 1][r] = v.y;
            as_s[c + 2][r] = v.z; as_s[c + 3][r] = v.w;
        }
        __syncthreads();
#pragma unroll
        for (int k = 0; k < 32; k++) {
            float a_[4], b_[4];
#pragma unroll
            for (int i = 0; i < 4; i++) a_[i] = xs[k][tg * 4 + i];
#pragma unroll
            for (int j = 0; j < 4; j++) b_[j] = as_s[k][rg * 4 + j];
#pragma unroll
            for (int i = 0; i < 4; i++)
#pragma unroll
                for (int j = 0; j < 4; j++) acc[i][j] += a_[i] * b_[j];
        }
    }

#pragma unroll
    for (int i = 0; i < 4; i++) {
        const int irow = tg * 4 + i;
        if (irow < rows) {
            const int t = perm_s[irow];
#pragma unroll
            for (int j = 0; j < 4; j++) {
                const int r = rg * 4 + j;
                float v = acc[i][j];
                if (blockIdx.y == 0) v += Ab[e * R_RANK + r];
                atomicAdd(&g_h[t * R_RANK + r], v);
            }
        }
    }
}

// ---------------------------------------------------------------------------
// Kernel 5: grouped LoRA B-stage + biases
// ---------------------------------------------------------------------------
__global__ __launch_bounds__(256)
void lorab_kernel(const float* __restrict__ Bw,
                  const float* __restrict__ Bb,
                  const float* __restrict__ bias,
                  int N, float* __restrict__ outb)
{
    const int slot = blockIdx.x;
    const int rows = g_tile_rows[slot];
    if (rows == 0) return;
    const int e     = g_tile_expert[slot];
    const int start = g_tile_start[slot];
    const int bn    = blockIdx.y * 128;

    __shared__ float hs[32][132];
    __shared__ float bs[32][132];
    __shared__ int   perm_s[128];

    const int tid = threadIdx.x;
    if (tid < 128) perm_s[tid] = (tid < rows) ? g_perm[start + tid] : 0;
    __syncthreads();

#pragma unroll
    for (int q = 0; q < 4; q++) {
        const int f = q * 256 + tid;
        const int i = f >> 3, c = (f & 7) * 4;
        float4 v = make_float4(0.f, 0.f, 0.f, 0.f);
        if (i < rows) v = *(const float4*)(g_h + perm_s[i] * R_RANK + c);
        hs[c + 0][i] = v.x; hs[c + 1][i] = v.y;
        hs[c + 2][i] = v.z; hs[c + 3][i] = v.w;
    }
#pragma unroll
    for (int q = 0; q < 4; q++) {
        const int f = q * 256 + tid;
        const int n = f >> 3, c = (f & 7) * 4;
        const float4 v = *(const float4*)(Bw + ((size_t)e * N + bn + n) * R_RANK + c);
        bs[c + 0][n] = v.x; bs[c + 1][n] = v.y;
        bs[c + 2][n] = v.z; bs[c + 3][n] = v.w;
    }
    __syncthreads();

    const int tx = tid & 15, ty = tid >> 4;
    float acc[8][8];
#pragma unroll
    for (int i = 0; i < 8; i++)
#pragma unroll
        for (int j = 0; j < 8; j++) acc[i][j] = 0.f;

#pragma unroll
    for (int k = 0; k < 32; k++) {
        const float4 af0 = *(const float4*)&hs[k][ty * 8];
        const float4 af1 = *(const float4*)&hs[k][ty * 8 + 4];
        const float4 bf0 = *(const float4*)&bs[k][tx * 8];
        const float4 bf1 = *(const float4*)&bs[k][tx * 8 + 4];
        const float a_[8] = {af0.x, af0.y, af0.z, af0.w, af1.x, af1.y, af1.z, af1.w};
        const float b_[8] = {bf0.x, bf0.y, bf0.z, bf0.w, bf1.x, bf1.y, bf1.z, bf1.w};
#pragma unroll
        for (int i = 0; i < 8; i++)
#pragma unroll
            for (int j = 0; j < 8; j++) acc[i][j] += a_[i] * b_[j];
    }

#pragma unroll
    for (int i = 0; i < 8; i++) {
        const int irow = ty * 8 + i;
        if (irow < rows) {
            const int t  = perm_s[irow];
            const int n0 = bn + tx * 8;
#pragma unroll
            for (int j = 0; j < 8; j++) {
                const int n = n0 + j;
                outb[(size_t)t * N + n] =
                    SCALING * (acc[i][j] + Bb[(size_t)e * N + n]) + bias[n];
            }
        }
    }
}

// ---------------------------------------------------------------------------
// Kernel 6: tcgen05 bf16x3 GEMM (TN): C = A*B^T + lora, optional GELU.
// 128(M) x 256(N) tile, BK=64, double-buffered smem, SS cg1 MMA, N=256 idesc.
// mode 1: GELU + write abuf fp32 + a_hi/a_lo bf16.  mode 0: write out fp32.
// ---------------------------------------------------------------------------
#define BN       256
#define SM_TMEM  0
#define SM_MBAR  16
#define SM_TILE  1024
#define A_PLANE  16384          // 128 rows x 64 bf16 x 2B
#define B_PLANE  32768          // 256 rows x 64 bf16 x 2B
#define STAGE    (2 * A_PLANE + 2 * B_PLANE)   // 98304
#define SMEM_BYTES (SM_TILE + 2 * STAGE)       // 197632

template <int ROWS>
__device__ __forceinline__ void load_plane(char* sdst, const __nv_bfloat16* g,
                                           int K, int tid)
{
#pragma unroll
    for (int q = 0; q < ROWS / 32; q++) {     // ROWS*8/256 uint4 per thread
        const int u = q * 256 + tid;
        const int row = u >> 3, c8 = u & 7;
        const uint4 v = *(const uint4*)(g + (size_t)row * K + c8 * 8);
        uint32_t off = row * 128 + c8 * 16;
        off ^= (off >> 3) & 0x70;            // SW128 swizzle
        *(uint4*)(sdst + off) = v;
    }
}

__global__ __launch_bounds__(256, 1)
void mma_gemm_kernel(const __nv_bfloat16* __restrict__ Ah,
                     const __nv_bfloat16* __restrict__ Al,
                     const __nv_bfloat16* __restrict__ Bh,
                     const __nv_bfloat16* __restrict__ Bl,
                     const float* __restrict__ lora,
                     int N, int K, int mode,
                     float* __restrict__ out_f32,
                     __nv_bfloat16* __restrict__ out_hi,
                     __nv_bfloat16* __restrict__ out_lo)
{
#if HAS_TCGEN05
    extern __shared__ char smem[];
    const uint32_t sbase = smem_to_u32(smem);
    const int tid  = threadIdx.x;
    const int wid  = tid >> 5;
    const int lane = tid & 31;
    const int bm = blockIdx.y * 128;
    const int bn = blockIdx.x * BN;

    if (wid == 0) TCGEN05_ALLOC(sbase + SM_TMEM, 256);
    if (tid == 0) {
        MBARRIER_INIT(sbase + SM_MBAR,     1);
        MBARRIER_INIT(sbase + SM_MBAR + 8, 1);
    }
    __syncthreads();
    uint32_t tmem;
    asm volatile("ld.shared.b32 %0, [%1];" : "=r"(tmem) : "r"(sbase + SM_TMEM));

    const __nv_bfloat16* gAh = Ah + (size_t)bm * K;
    const __nv_bfloat16* gAl = Al + (size_t)bm * K;
    const __nv_bfloat16* gBh = Bh + (size_t)bn * K;
    const __nv_bfloat16* gBl = Bl + (size_t)bn * K;

    const int nch = K / 64;
    for (int c = 0; c < nch; c++) {
        const int buf = c & 1;
        if (c >= 2)
            MBARRIER_WAIT_PARITY(sbase + SM_MBAR + buf * 8, ((c >> 1) - 1) & 1);

        char* sb = smem + SM_TILE + buf * STAGE;
        load_plane<128>(sb,                         gAh + c * 64, K, tid);
        load_plane<128>(sb + A_PLANE,               gAl + c * 64, K, tid);
        load_plane<256>(sb + 2 * A_PLANE,           gBh + c * 64, K, tid);
        load_plane<256>(sb + 2 * A_PLANE + B_PLANE, gBl + c * 64, K, tid);
        FENCE_PROXY_ASYNC();
        __syncthreads();

        if (wid == 0) {
            if (elect_one_pred()) {
                const uint32_t su = sbase + SM_TILE + buf * STAGE;
                const uint64_t dAh = MAKE_SMEM_DESC(su);
                const uint64_t dAl = MAKE_SMEM_DESC(su + A_PLANE);
                const uint64_t dBh = MAKE_SMEM_DESC(su + 2 * A_PLANE);
                const uint64_t dBl = MAKE_SMEM_DESC(su + 2 * A_PLANE + B_PLANE);
#pragma unroll
                for (int j = 0; j < 4; j++) {       // K=16 per MMA
                    const uint64_t oj = (uint64_t)(j * 2);
                    mma_f16_ss(tmem, dAh + oj, dBh + oj, (c == 0 && j == 0) ? 0u : 1u);
                    mma_f16_ss(tmem, dAh + oj, dBl + oj, 1u);
                    mma_f16_ss(tmem, dAl + oj, dBh + oj, 1u);
                }
                TCGEN05_COMMIT(sbase + SM_MBAR + buf * 8);
            }
        }
    }

    // wait for final chunk's commit (tcgen05 MMAs complete in issue order)
    {
        const int lc = nch - 1;
        MBARRIER_WAIT_PARITY(sbase + SM_MBAR + (lc & 1) * 8, (lc >> 1) & 1);
    }
    TCGEN05_FENCE_AFTER();

    // epilogue: warpgroup 0 reads TMEM D (warp w -> rows w*32..w*32+31)
    if (wid < 4) {
        const int m = bm + wid * 32 + lane;
#pragma unroll
        for (int cc = 0; cc < BN; cc += 32) {
            uint32_t dr[32];
            TCGEN05_LD_32X32B_X32(dr, tmem + cc);
            TCGEN05_WAIT_LD();

            const float4* lp = (const float4*)(lora + (size_t)m * N + bn + cc);
            if (mode) {
                float4*        op = (float4*)(out_f32 + (size_t)m * N + bn + cc);
                __nv_bfloat16 hb[32], lb[32];
#pragma unroll
                for (int g = 0; g < 8; g++) {
                    const float4 l = lp[g];
                    float v[4];
                    v[0] = __uint_as_float(dr[g * 4 + 0]) + l.x;
                    v[1] = __uint_as_float(dr[g * 4 + 1]) + l.y;
                    v[2] = __uint_as_float(dr[g * 4 + 2]) + l.z;
                    v[3] = __uint_as_float(dr[g * 4 + 3]) + l.w;
#pragma unroll
                    for (int k = 0; k < 4; k++) {
                        v[k] = 0.5f * v[k] * (1.f + erff(v[k] * 0.70710678118654752f));
                        const __nv_bfloat16 h = __float2bfloat16(v[k]);
                        hb[g * 4 + k] = h;
                        lb[g * 4 + k] = __float2bfloat16(v[k] - __bfloat162float(h));
                    }
                    op[g] = make_float4(v[0], v[1], v[2], v[3]);
                }
                uint4* hp = (uint4*)(out_hi + (size_t)m * N + bn + cc);
                uint4* lq = (uint4*)(out_lo + (size_t)m * N + bn + cc);
#pragma unroll
                for (int g = 0; g < 4; g++) {
                    hp[g] = ((uint4*)hb)[g];
                    lq[g] = ((uint4*)lb)[g];
                }
            } else {
                float4* op = (float4*)(out_f32 + (size_t)m * N + bn + cc);
#pragma unroll
                for (int g = 0; g < 8; g++) {
                    const float4 l = lp[g];
                    op[g] = make_float4(__uint_as_float(dr[g * 4 + 0]) + l.x,
                                        __uint_as_float(dr[g * 4 + 1]) + l.y,
                                        __uint_as_float(dr[g * 4 + 2]) + l.z,
                                        __uint_as_float(dr[g * 4 + 3]) + l.w);
                }
            }
        }
        TCGEN05_FENCE_BEFORE();
    }

    __syncthreads();
    if (wid == 0) {
        TCGEN05_RELINQUISH();
        TCGEN05_DEALLOC(tmem, 256);
    }
#else
    // Portable fallback for the generic compute_103 PTX stage. Never executed
    // on GB300 (the sm_103a cubin takes the tcgen05 path above); correct if
    // ever JIT'd from PTX.
    const int tid = threadIdx.x;
    const int bm = blockIdx.y * 128;
    const int bn = blockIdx.x * BN;
    for (int i = tid; i < 128 * BN; i += 256) {
        const int m = bm + (i / BN);
        const int n = bn + (i % BN);
        float s = 0.f;
        for (int k = 0; k < K; k++) {
            const float a = __bfloat162float(Ah[(size_t)m * K + k]) +
                            __bfloat162float(Al[(size_t)m * K + k]);
            const float b = __bfloat162float(Bh[(size_t)n * K + k]) +
                            __bfloat162float(Bl[(size_t)n * K + k]);
            s += a * b;
        }
        float v = s + lora[(size_t)m * N + n];
        if (mode) {
            v = 0.5f * v * (1.f + erff(v * 0.70710678118654752f));
            const __nv_bfloat16 h = __float2bfloat16(v);
            out_hi[(size_t)m * N + n] = h;
            out_lo[(size_t)m * N + n] = __float2bfloat16(v - __bfloat162float(h));
        }
        out_f32[(size_t)m * N + n] = v;
    }
#endif
}

// ---------------------------------------------------------------------------
// Launch sequence
// ---------------------------------------------------------------------------
extern "C" void kernel_launch(void* const* d_in, const int* in_sizes, int n_in,
                              void* d_out, int out_size)
{
    (void)in_sizes; (void)n_in; (void)out_size;
    const float* x     = (const float*)d_in[0];
    const float* rw    = (const float*)d_in[1];
    const float* rb    = (const float*)d_in[2];
    const float* fc1w  = (const float*)d_in[3];
    const float* fc1b  = (const float*)d_in[4];
    const float* fc2w  = (const float*)d_in[5];
    const float* fc2b  = (const float*)d_in[6];
    const float* A_dn  = (const float*)d_in[7];
    const float* Ab_dn = (const float*)d_in[8];
    const float* B_dn  = (const float*)d_in[9];
    const float* Bb_dn = (const float*)d_in[10];
    const float* A_up  = (const float*)d_in[11];
    const float* Ab_up = (const float*)d_in[12];
    const float* B_up  = (const float*)d_in[13];
    const float* Bb_up = (const float*)d_in[14];

    float* out    = (float*)d_out;
    float* out_up = out;
    float* out_rt = out + (size_t)T_TOK * D_IN;
    float* out_ec = out_rt + (size_t)T_TOK * E_EXP;

    float *abuf_p = nullptr, *lora_p = nullptr;
    __nv_bfloat16 *xhi, *xlo, *w1hi, *w1lo, *w2hi, *w2lo, *ahi, *alo;
    cudaGetSymbolAddress((void**)&abuf_p, g_abuf);
    cudaGetSymbolAddress((void**)&lora_p, g_lora);
    cudaGetSymbolAddress((void**)&xhi,  g_xhi);
    cudaGetSymbolAddress((void**)&xlo,  g_xlo);
    cudaGetSymbolAddress((void**)&w1hi, g_w1hi);
    cudaGetSymbolAddress((void**)&w1lo, g_w1lo);
    cudaGetSymbolAddress((void**)&w2hi, g_w2hi);
    cudaGetSymbolAddress((void**)&w2lo, g_w2lo);
    cudaGetSymbolAddress((void**)&ahi,  g_ahi);
    cudaGetSymbolAddress((void**)&alo,  g_alo);

    cudaFuncSetAttribute(mma_gemm_kernel,
                         cudaFuncAttributeMaxDynamicSharedMemorySize, SMEM_BYTES);

    // hi/lo splits of x and the frozen weights
    const int n4_xd = T_TOK * D_IN / 4;      // == H*D/4 == D*H/4
    cvt_hilo_kernel<<<(n4_xd + 255) / 256, 256>>>(x,    xhi,  xlo,  n4_xd);
    cvt_hilo_kernel<<<(n4_xd + 255) / 256, 256>>>(fc1w, w1hi, w1lo, H_DIM * D_IN / 4);
    cvt_hilo_kernel<<<(n4_xd + 255) / 256, 256>>>(fc2w, w2hi, w2lo, D_IN * H_DIM / 4);

    // router + grouping
    router_kernel<<<T_TOK, 256>>>(x, rw, rb, out_rt, out_ec);
    group_kernel<<<1, 256>>>();

    // ---- down: LoRA staging then fc1 GEMM (tensor cores) + GELU ----
    zero_h_kernel<<<(T_TOK * R_RANK + 255) / 256, 256>>>();
    rank_kernel<<<dim3(MAX_TILES, D_IN / 64), 256>>>(x, D_IN, 64, A_dn, Ab_dn);
    lorab_kernel<<<dim3(MAX_TILES, H_DIM / 128), 256>>>(B_dn, Bb_dn, fc1b, H_DIM, lora_p);
    mma_gemm_kernel<<<dim3(H_DIM / BN, T_TOK / 128), 256, SMEM_BYTES>>>(
        xhi, xlo, w1hi, w1lo, lora_p, H_DIM, D_IN, 1, abuf_p, ahi, alo);

    // ---- up: LoRA staging then fc2 GEMM (tensor cores) ----
    zero_h_kernel<<<(T_TOK * R_RANK + 255) / 256, 256>>>();
    rank_kernel<<<dim3(MAX_TILES, H_DIM / 64), 256>>>(abuf_p, H_DIM, 64, A_up, Ab_up);
    lorab_kernel<<<dim3(MAX_TILES, D_IN / 128), 256>>>(B_up, Bb_up, fc2b, D_IN, lora_p);
    mma_gemm_kernel<<<dim3(D_IN / BN, T_TOK / 128), 256, SMEM_BYTES>>>(
        ahi, alo, w2hi, w2lo, lora_p, D_IN, H_DIM, 0, out_up, nullptr, nullptr);
}

// round 15
// speedup vs baseline: 1.0027x; 1.0027x over previous
#include <cuda_runtime.h>
#include <cuda_bf16.h>
#include <math.h>
#include <stdint.h>

// ---------------------------------------------------------------------------
// Arch gate: tcgen05/TMEM are sm_103a-SPECIFIC. The harness build also emits
// a generic compute_103 PTX stage, which must not see tcgen05 instructions.
// ---------------------------------------------------------------------------
#if defined(__CUDA_ARCH__) && \
    (defined(__CUDA_ARCH_FEAT_SM103_ALL) || defined(__CUDA_ARCH_FEAT_SM100_ALL) || \
     defined(__CUDA_ARCH_SPECIFIC__))
#define HAS_TCGEN05 1
#else
#define HAS_TCGEN05 0
#endif

// ---------------------------------------------------------------------------
// Problem constants
// ---------------------------------------------------------------------------
#define T_TOK   4096
#define D_IN    1024
#define H_DIM   4096
#define E_EXP   8
#define R_RANK  32
#define SCALING 0.03125f
#define MAX_TILES 40

// ---------------------------------------------------------------------------
// Device scratch
// ---------------------------------------------------------------------------
__device__ int   g_idx[T_TOK];
__device__ int   g_perm[T_TOK];
__device__ int   g_tile_expert[MAX_TILES];
__device__ int   g_tile_start[MAX_TILES];
__device__ int   g_tile_rows[MAX_TILES];
__device__ float g_h[T_TOK * R_RANK];
__device__ float g_abuf[(size_t)T_TOK * H_DIM];      // gelu(down) fp32 (LoRA input)
__device__ float g_lora[(size_t)T_TOK * H_DIM];      // lora + bias staging
// hi/lo bf16 split planes
__device__ __nv_bfloat16 g_xhi[(size_t)T_TOK * D_IN];
__device__ __nv_bfloat16 g_xlo[(size_t)T_TOK * D_IN];
__device__ __nv_bfloat16 g_w1hi[(size_t)H_DIM * D_IN];
__device__ __nv_bfloat16 g_w1lo[(size_t)H_DIM * D_IN];
__device__ __nv_bfloat16 g_w2hi[(size_t)D_IN * H_DIM];
__device__ __nv_bfloat16 g_w2lo[(size_t)D_IN * H_DIM];
__device__ __nv_bfloat16 g_ahi[(size_t)T_TOK * H_DIM];
__device__ __nv_bfloat16 g_alo[(size_t)T_TOK * H_DIM];

// ---------------------------------------------------------------------------
// PTX helpers
// ---------------------------------------------------------------------------
__device__ __forceinline__ uint32_t elect_one_pred() {
    uint32_t pred;
    asm volatile(
        "{\n\t.reg .pred p;\n\t"
        "elect.sync _|p, 0xFFFFFFFF;\n\t"
        "selp.b32 %0, 1, 0, p;\n\t}"
        : "=r"(pred));
    return pred;
}
__device__ __forceinline__ uint32_t smem_to_u32(const void* p) {
    uint32_t a;
    asm("{ .reg .u64 t; cvta.to.shared.u64 t, %1; cvt.u32.u64 %0, t; }"
        : "=r"(a) : "l"(p));
    return a;
}
#define MBARRIER_INIT(addr, cnt) \
    asm volatile("mbarrier.init.shared.b64 [%0], %1;" :: "r"((uint32_t)(addr)), "r"((uint32_t)(cnt)) : "memory")
#define MBARRIER_WAIT_PARITY(mbar_smem_addr, phase_parity) do { \
    uint32_t _mbar = (uint32_t)(mbar_smem_addr); \
    uint32_t _parity = (uint32_t)(phase_parity); \
    uint32_t _done; \
    asm volatile( \
        "{\n\t.reg .pred p;\n\t" \
        "mbarrier.try_wait.parity.acquire.cta.shared::cta.b64 p, [%1], %2;\n\t" \
        "selp.b32 %0, 1, 0, p;\n\t}" \
        : "=r"(_done) : "r"(_mbar), "r"(_parity) : "memory"); \
    if (!_done) { \
        asm volatile( \
            "{\n\t.reg .pred P1;\n\t" \
            "WAIT_LOOP_%=:\n\t" \
            "mbarrier.try_wait.parity.acquire.cta.shared::cta.b64 P1, [%0], %1, 0x989680;\n\t" \
            "@P1 bra.uni WAIT_DONE_%=;\n\t" \
            "bra.uni WAIT_LOOP_%=;\n\t" \
            "WAIT_DONE_%=:\n\t}" \
            :: "r"(_mbar), "r"(_parity) : "memory"); \
    } \
} while(0)
#define FENCE_PROXY_ASYNC()    asm volatile("fence.proxy.async.shared::cta;" ::: "memory")

#if HAS_TCGEN05
#define TCGEN05_ALLOC(sa, n) \
    asm volatile("tcgen05.alloc.cta_group::1.sync.aligned.shared::cta.b32 [%0], %1;" \
                 :: "r"((uint32_t)(sa)), "r"((uint32_t)(n)) : "memory")
#define TCGEN05_DEALLOC(t, n) \
    asm volatile("tcgen05.dealloc.cta_group::1.sync.aligned.b32 %0, %1;" :: "r"(t), "r"(n))
#define TCGEN05_RELINQUISH() \
    asm volatile("tcgen05.relinquish_alloc_permit.cta_group::1.sync.aligned;")
#define TCGEN05_COMMIT(mb) \
    asm volatile("tcgen05.commit.cta_group::1.mbarrier::arrive::one.shared::cluster.b64 [%0];" \
                 :: "r"((uint32_t)(mb)) : "memory")
#define TCGEN05_FENCE_AFTER()  asm volatile("tcgen05.fence::after_thread_sync;" ::: "memory")
#define TCGEN05_FENCE_BEFORE() asm volatile("tcgen05.fence::before_thread_sync;" ::: "memory")
#define TCGEN05_WAIT_LD()      asm volatile("tcgen05.wait::ld.sync.aligned;" ::: "memory")
#define TCGEN05_LD_32X32B_X32(r, ta) \
    asm volatile( \
        "tcgen05.ld.sync.aligned.32x32b.x32.b32 " \
        "{%0, %1, %2, %3, %4, %5, %6, %7, " \
        " %8, %9, %10, %11, %12, %13, %14, %15, " \
        " %16, %17, %18, %19, %20, %21, %22, %23, " \
        " %24, %25, %26, %27, %28, %29, %30, %31}, [%32];" \
        : "=r"((r)[0]),  "=r"((r)[1]),  "=r"((r)[2]),  "=r"((r)[3]), \
          "=r"((r)[4]),  "=r"((r)[5]),  "=r"((r)[6]),  "=r"((r)[7]), \
          "=r"((r)[8]),  "=r"((r)[9]),  "=r"((r)[10]), "=r"((r)[11]), \
          "=r"((r)[12]), "=r"((r)[13]), "=r"((r)[14]), "=r"((r)[15]), \
          "=r"((r)[16]), "=r"((r)[17]), "=r"((r)[18]), "=r"((r)[19]), \
          "=r"((r)[20]), "=r"((r)[21]), "=r"((r)[22]), "=r"((r)[23]), \
          "=r"((r)[24]), "=r"((r)[25]), "=r"((r)[26]), "=r"((r)[27]), \
          "=r"((r)[28]), "=r"((r)[29]), "=r"((r)[30]), "=r"((r)[31]) \
        : "r"(ta))

// SW128 K-major smem descriptor (version=1, SBO=64, LBO=1)
static constexpr uint64_t SMEM_DESC_BASE_SW128 =
    (uint64_t(2) << 61) | (uint64_t(1) << 46) | (uint64_t(64) << 32) | (uint64_t(1) << 16);
#define MAKE_SMEM_DESC(a) (SMEM_DESC_BASE_SW128 | ((uint64_t)((a) >> 4) & 0x3FFF))

// idesc: kind::f16, bf16 a/b, f32 accum, M=128, N=256
// (1<<4)|(1<<7)|(1<<10)|((256/8)<<17)|((128/16)<<24)
#define MMA_IDESC 0x8400490u

__device__ __forceinline__ void mma_f16_ss(uint32_t d, uint64_t a, uint64_t b,
                                           uint32_t en)
{
    asm volatile(
        "{\n\t.reg .pred p;\n\t"
        "setp.ne.u32 p, %5, 0;\n\t"
        "tcgen05.mma.cta_group::1.kind::f16 [%0], %1, %2, %3, {%4, %4, %4, %4}, p;\n\t}"
        :: "r"(d), "l"(a), "l"(b), "r"(MMA_IDESC), "r"(0u), "r"(en)
        : "memory");
}
#endif  // HAS_TCGEN05

// ---------------------------------------------------------------------------
// Kernel 1: router
// ---------------------------------------------------------------------------
__global__ void router_kernel(const float* __restrict__ x,
                              const float* __restrict__ rw,
                              const float* __restrict__ rb,
                              float* __restrict__ routing,
                              float* __restrict__ ec)
{
    const int t = blockIdx.x;
    __shared__ float xs[D_IN];
    __shared__ float lg[E_EXP];
    const int tid = threadIdx.x;

    ((float4*)xs)[tid] = ((const float4*)(x + (size_t)t * D_IN))[tid];
    __syncthreads();

    const int w = tid >> 5, lane = tid & 31;
    const float* wrow = rw + (size_t)w * D_IN;
    float s = 0.f;
    for (int d = lane; d < D_IN; d += 32) s += xs[d] * wrow[d];
#pragma unroll
    for (int o = 16; o; o >>= 1) s += __shfl_xor_sync(0xFFFFFFFFu, s, o);
    if (lane == 0) lg[w] = s + rb[w];
    __syncthreads();

    if (tid == 0) {
        float m = lg[0]; int am = 0;
#pragma unroll
        for (int e = 1; e < E_EXP; e++) if (lg[e] > m) { m = lg[e]; am = e; }
        float ex[E_EXP]; float den = 0.f;
#pragma unroll
        for (int e = 0; e < E_EXP; e++) { ex[e] = expf(lg[e] - m); den += ex[e]; }
        const float inv = 1.f / den;
#pragma unroll
        for (int e = 0; e < E_EXP; e++) {
            const float r = ex[e] * inv;
            routing[t * E_EXP + e] = r;
            const float msk = (e == am) ? 1.f : 0.f;
            ec[t * E_EXP + e] = (msk - r) + r;
        }
        g_idx[t] = am;
    }
}

// ---------------------------------------------------------------------------
// Kernel 2: group tokens by expert
// ---------------------------------------------------------------------------
__global__ void group_kernel()
{
    __shared__ int cnt[E_EXP];
    __shared__ int base[E_EXP];
    const int tid = threadIdx.x;
    if (tid < E_EXP) cnt[tid] = 0;
    __syncthreads();
    for (int t = tid; t < T_TOK; t += 256) atomicAdd(&cnt[g_idx[t]], 1);
    __syncthreads();
    if (tid == 0) {
        int off = 0, slot = 0;
        for (int e = 0; e < E_EXP; e++) {
            base[e] = off;
            const int c = cnt[e];
            for (int s = 0; s < c; s += 128) {
                g_tile_expert[slot] = e;
                g_tile_start[slot]  = off + s;
                g_tile_rows[slot]   = min(128, c - s);
                slot++;
            }
            off += c;
        }
        for (; slot < MAX_TILES; slot++) g_tile_rows[slot] = 0;
    }
    __syncthreads();
    if (tid < E_EXP) cnt[tid] = base[tid];
    __syncthreads();
    for (int t = tid; t < T_TOK; t += 256) {
        const int e = g_idx[t];
        const int pos = atomicAdd(&cnt[e], 1);
        g_perm[pos] = t;
    }
}

// ---------------------------------------------------------------------------
// Kernel 3: zero rank-stage buffer
// ---------------------------------------------------------------------------
__global__ void zero_h_kernel()
{
    const int i = blockIdx.x * blockDim.x + threadIdx.x;
    if (i < T_TOK * R_RANK) g_h[i] = 0.f;
}

// ---------------------------------------------------------------------------
// Kernel: fp32 -> bf16 hi/lo split (vectorized x4)
// ---------------------------------------------------------------------------
__global__ void cvt_hilo_kernel(const float* __restrict__ s,
                                __nv_bfloat16* __restrict__ hi,
                                __nv_bfloat16* __restrict__ lo, int n4)
{
    const int i = blockIdx.x * blockDim.x + threadIdx.x;
    if (i >= n4) return;
    const float4 f = ((const float4*)s)[i];
    __nv_bfloat16 h[4], l[4];
    h[0] = __float2bfloat16(f.x); l[0] = __float2bfloat16(f.x - __bfloat162float(h[0]));
    h[1] = __float2bfloat16(f.y); l[1] = __float2bfloat16(f.y - __bfloat162float(h[1]));
    h[2] = __float2bfloat16(f.z); l[2] = __float2bfloat16(f.z - __bfloat162float(h[2]));
    h[3] = __float2bfloat16(f.w); l[3] = __float2bfloat16(f.w - __bfloat162float(h[3]));
    ((uint2*)hi)[i] = *(uint2*)h;
    ((uint2*)lo)[i] = *(uint2*)l;
}

// ---------------------------------------------------------------------------
// Kernel 4: grouped rank stage (k-split 64 for occupancy)
// ---------------------------------------------------------------------------
__global__ void rank_kernel(const float* __restrict__ in, int K, int kchunk,
                            const float* __restrict__ A,
                            const float* __restrict__ Ab)
{
    const int slot = blockIdx.x;
    const int rows = g_tile_rows[slot];
    if (rows == 0) return;
    const int e     = g_tile_expert[slot];
    const int start = g_tile_start[slot];
    const int k0    = blockIdx.y * kchunk;

    __shared__ float xs[32][132];
    __shared__ float as_s[32][36];
    __shared__ int   perm_s[128];

    const int tid = threadIdx.x;
    if (tid < 128) perm_s[tid] = (tid < rows) ? g_perm[start + tid] : 0;
    const int tg = tid >> 3;
    const int rg = tid & 7;
    float acc[4][4];
#pragma unroll
    for (int i = 0; i < 4; i++)
#pragma unroll
        for (int j = 0; j < 4; j++) acc[i][j] = 0.f;
    __syncthreads();

    for (int kk = k0; kk < k0 + kchunk; kk += 32) {
        __syncthreads();
#pragma unroll
        for (int q = 0; q < 4; q++) {
            const int f = q * 256 + tid;
            const int i = f >> 3, c = (f & 7) * 4;
            float4 v = make_float4(0.f, 0.f, 0.f, 0.f);
            if (i < rows) v = *(const float4*)(in + (size_t)perm_s[i] * K + kk + c);
            xs[c + 0][i] = v.x; xs[c + 1][i] = v.y;
            xs[c + 2][i] = v.z; xs[c + 3][i] = v.w;
        }
        {
            const int r = tid >> 3, c = (tid & 7) * 4;
            const float4 v = *(const float4*)(A + ((size_t)e * R_RANK + r) * K + kk + c);
            as_s[c + 0][r] = v.x; as_s[c + 1][r] = v.y;
            as_s[c + 2][r] = v.z; as_s[c + 3][r] = v.w;
        }
        __syncthreads();
#pragma unroll
        for (int k = 0; k < 32; k++) {
            float a_[4], b_[4];
#pragma unroll
            for (int i = 0; i < 4; i++) a_[i] = xs[k][tg * 4 + i];
#pragma unroll
            for (int j = 0; j < 4; j++) b_[j] = as_s[k][rg * 4 + j];
#pragma unroll
            for (int i = 0; i < 4; i++)
#pragma unroll
                for (int j = 0; j < 4; j++) acc[i][j] += a_[i] * b_[j];
        }
    }

#pragma unroll
    for (int i = 0; i < 4; i++) {
        const int irow = tg * 4 + i;
        if (irow < rows) {
            const int t = perm_s[irow];
#pragma unroll
            for (int j = 0; j < 4; j++) {
                const int r = rg * 4 + j;
                float v = acc[i][j];
                if (blockIdx.y == 0) v += Ab[e * R_RANK + r];
                atomicAdd(&g_h[t * R_RANK + r], v);
            }
        }
    }
}

// ---------------------------------------------------------------------------
// Kernel 5: grouped LoRA B-stage + biases
// ---------------------------------------------------------------------------
__global__ __launch_bounds__(256)
void lorab_kernel(const float* __restrict__ Bw,
                  const float* __restrict__ Bb,
                  const float* __restrict__ bias,
                  int N, float* __restrict__ outb)
{
    const int slot = blockIdx.x;
    const int rows = g_tile_rows[slot];
    if (rows == 0) return;
    const int e     = g_tile_expert[slot];
    const int start = g_tile_start[slot];
    const int bn    = blockIdx.y * 128;

    __shared__ float hs[32][132];
    __shared__ float bs[32][132];
    __shared__ int   perm_s[128];

    const int tid = threadIdx.x;
    if (tid < 128) perm_s[tid] = (tid < rows) ? g_perm[start + tid] : 0;
    __syncthreads();

#pragma unroll
    for (int q = 0; q < 4; q++) {
        const int f = q * 256 + tid;
        const int i = f >> 3, c = (f & 7) * 4;
        float4 v = make_float4(0.f, 0.f, 0.f, 0.f);
        if (i < rows) v = *(const float4*)(g_h + perm_s[i] * R_RANK + c);
        hs[c + 0][i] = v.x; hs[c + 1][i] = v.y;
        hs[c + 2][i] = v.z; hs[c + 3][i] = v.w;
    }
#pragma unroll
    for (int q = 0; q < 4; q++) {
        const int f = q * 256 + tid;
        const int n = f >> 3, c = (f & 7) * 4;
        const float4 v = *(const float4*)(Bw + ((size_t)e * N + bn + n) * R_RANK + c);
        bs[c + 0][n] = v.x; bs[c + 1][n] = v.y;
        bs[c + 2][n] = v.z; bs[c + 3][n] = v.w;
    }
    __syncthreads();

    const int tx = tid & 15, ty = tid >> 4;
    float acc[8][8];
#pragma unroll
    for (int i = 0; i < 8; i++)
#pragma unroll
        for (int j = 0; j < 8; j++) acc[i][j] = 0.f;

#pragma unroll
    for (int k = 0; k < 32; k++) {
        const float4 af0 = *(const float4*)&hs[k][ty * 8];
        const float4 af1 = *(const float4*)&hs[k][ty * 8 + 4];
        const float4 bf0 = *(const float4*)&bs[k][tx * 8];
        const float4 bf1 = *(const float4*)&bs[k][tx * 8 + 4];
        const float a_[8] = {af0.x, af0.y, af0.z, af0.w, af1.x, af1.y, af1.z, af1.w};
        const float b_[8] = {bf0.x, bf0.y, bf0.z, bf0.w, bf1.x, bf1.y, bf1.z, bf1.w};
#pragma unroll
        for (int i = 0; i < 8; i++)
#pragma unroll
            for (int j = 0; j < 8; j++) acc[i][j] += a_[i] * b_[j];
    }

#pragma unroll
    for (int i = 0; i < 8; i++) {
        const int irow = ty * 8 + i;
        if (irow < rows) {
            const int t  = perm_s[irow];
            const int n0 = bn + tx * 8;
#pragma unroll
            for (int j = 0; j < 8; j++) {
                const int n = n0 + j;
                outb[(size_t)t * N + n] =
                    SCALING * (acc[i][j] + Bb[(size_t)e * N + n]) + bias[n];
            }
        }
    }
}

// ---------------------------------------------------------------------------
// Kernel 6: tcgen05 bf16x3 GEMM (TN): C = A*B^T + lora, optional GELU.
// 128(M) x 256(N) tile, BK=64, double-buffered smem, SS cg1 MMA, N=256 idesc.
// mode 1: GELU + write abuf fp32 + a_hi/a_lo bf16.  mode 0: write out fp32.
// ---------------------------------------------------------------------------
#define BN       256
#define SM_TMEM  0
#define SM_MBAR  16
#define SM_TILE  1024
#define A_PLANE  16384          // 128 rows x 64 bf16 x 2B
#define B_PLANE  32768          // 256 rows x 64 bf16 x 2B
#define STAGE    (2 * A_PLANE + 2 * B_PLANE)   // 98304
#define SMEM_BYTES (SM_TILE + 2 * STAGE)       // 197632

template <int ROWS>
__device__ __forceinline__ void load_plane(char* sdst, const __nv_bfloat16* g,
                                           int K, int tid)
{
#pragma unroll
    for (int q = 0; q < ROWS / 32; q++) {     // ROWS*8/256 uint4 per thread
        const int u = q * 256 + tid;
        const int row = u >> 3, c8 = u & 7;
        const uint4 v = *(const uint4*)(g + (size_t)row * K + c8 * 8);
        uint32_t off = row * 128 + c8 * 16;
        off ^= (off >> 3) & 0x70;            // SW128 swizzle
        *(uint4*)(sdst + off) = v;
    }
}

__global__ __launch_bounds__(256, 1)
void mma_gemm_kernel(const __nv_bfloat16* __restrict__ Ah,
                     const __nv_bfloat16* __restrict__ Al,
                     const __nv_bfloat16* __restrict__ Bh,
                     const __nv_bfloat16* __restrict__ Bl,
                     const float* __restrict__ lora,
                     int N, int K, int mode,
                     float* __restrict__ out_f32,
                     __nv_bfloat16* __restrict__ out_hi,
                     __nv_bfloat16* __restrict__ out_lo)
{
#if HAS_TCGEN05
    extern __shared__ char smem[];
    const uint32_t sbase = smem_to_u32(smem);
    const int tid  = threadIdx.x;
    const int wid  = tid >> 5;
    const int lane = tid & 31;
    const int bm = blockIdx.y * 128;
    const int bn = blockIdx.x * BN;

    if (wid == 0) TCGEN05_ALLOC(sbase + SM_TMEM, 256);
    if (tid == 0) {
        MBARRIER_INIT(sbase + SM_MBAR,     1);
        MBARRIER_INIT(sbase + SM_MBAR + 8, 1);
    }
    __syncthreads();
    uint32_t tmem;
    asm volatile("ld.shared.b32 %0, [%1];" : "=r"(tmem) : "r"(sbase + SM_TMEM));

    const __nv_bfloat16* gAh = Ah + (size_t)bm * K;
    const __nv_bfloat16* gAl = Al + (size_t)bm * K;
    const __nv_bfloat16* gBh = Bh + (size_t)bn * K;
    const __nv_bfloat16* gBl = Bl + (size_t)bn * K;

    const int nch = K / 64;
    for (int c = 0; c < nch; c++) {
        const int buf = c & 1;
        if (c >= 2)
            MBARRIER_WAIT_PARITY(sbase + SM_MBAR + buf * 8, ((c >> 1) - 1) & 1);

        char* sb = smem + SM_TILE + buf * STAGE;
        load_plane<128>(sb,                         gAh + c * 64, K, tid);
        load_plane<128>(sb + A_PLANE,               gAl + c * 64, K, tid);
        load_plane<256>(sb + 2 * A_PLANE,           gBh + c * 64, K, tid);
        load_plane<256>(sb + 2 * A_PLANE + B_PLANE, gBl + c * 64, K, tid);
        FENCE_PROXY_ASYNC();
        __syncthreads();

        if (wid == 0) {
            if (elect_one_pred()) {
                const uint32_t su = sbase + SM_TILE + buf * STAGE;
                const uint64_t dAh = MAKE_SMEM_DESC(su);
                const uint64_t dAl = MAKE_SMEM_DESC(su + A_PLANE);
                const uint64_t dBh = MAKE_SMEM_DESC(su + 2 * A_PLANE);
                const uint64_t dBl = MAKE_SMEM_DESC(su + 2 * A_PLANE + B_PLANE);
#pragma unroll
                for (int j = 0; j < 4; j++) {       // K=16 per MMA
                    const uint64_t oj = (uint64_t)(j * 2);
                    mma_f16_ss(tmem, dAh + oj, dBh + oj, (c == 0 && j == 0) ? 0u : 1u);
                    mma_f16_ss(tmem, dAh + oj, dBl + oj, 1u);
                    mma_f16_ss(tmem, dAl + oj, dBh + oj, 1u);
                }
                TCGEN05_COMMIT(sbase + SM_MBAR + buf * 8);
            }
        }
    }

    // wait for final chunk's commit (tcgen05 MMAs complete in issue order)
    {
        const int lc = nch - 1;
        MBARRIER_WAIT_PARITY(sbase + SM_MBAR + (lc & 1) * 8, (lc >> 1) & 1);
    }
    TCGEN05_FENCE_AFTER();

    // epilogue: warpgroup 0 reads TMEM D (warp w -> rows w*32..w*32+31)
    if (wid < 4) {
        const int m = bm + wid * 32 + lane;
#pragma unroll
        for (int cc = 0; cc < BN; cc += 32) {
            uint32_t dr[32];
            TCGEN05_LD_32X32B_X32(dr, tmem + cc);
            TCGEN05_WAIT_LD();

            const float4* lp = (const float4*)(lora + (size_t)m * N + bn + cc);
            if (mode) {
                float4*        op = (float4*)(out_f32 + (size_t)m * N + bn + cc);
                __nv_bfloat16 hb[32], lb[32];
#pragma unroll
                for (int g = 0; g < 8; g++) {
                    const float4 l = lp[g];
                    float v[4];
                    v[0] = __uint_as_float(dr[g * 4 + 0]) + l.x;
                    v[1] = __uint_as_float(dr[g * 4 + 1]) + l.y;
                    v[2] = __uint_as_float(dr[g * 4 + 2]) + l.z;
                    v[3] = __uint_as_float(dr[g * 4 + 3]) + l.w;
#pragma unroll
                    for (int k = 0; k < 4; k++) {
                        v[k] = 0.5f * v[k] * (1.f + erff(v[k] * 0.70710678118654752f));
                        const __nv_bfloat16 h = __float2bfloat16(v[k]);
                        hb[g * 4 + k] = h;
                        lb[g * 4 + k] = __float2bfloat16(v[k] - __bfloat162float(h));
                    }
                    op[g] = make_float4(v[0], v[1], v[2], v[3]);
                }
                uint4* hp = (uint4*)(out_hi + (size_t)m * N + bn + cc);
                uint4* lq = (uint4*)(out_lo + (size_t)m * N + bn + cc);
#pragma unroll
                for (int g = 0; g < 4; g++) {
                    hp[g] = ((uint4*)hb)[g];
                    lq[g] = ((uint4*)lb)[g];
                }
            } else {
                float4* op = (float4*)(out_f32 + (size_t)m * N + bn + cc);
#pragma unroll
                for (int g = 0; g < 8; g++) {
                    const float4 l = lp[g];
                    op[g] = make_float4(__uint_as_float(dr[g * 4 + 0]) + l.x,
                                        __uint_as_float(dr[g * 4 + 1]) + l.y,
                                        __uint_as_float(dr[g * 4 + 2]) + l.z,
                                        __uint_as_float(dr[g * 4 + 3]) + l.w);
                }
            }
        }
        TCGEN05_FENCE_BEFORE();
    }

    __syncthreads();
    if (wid == 0) {
        TCGEN05_RELINQUISH();
        TCGEN05_DEALLOC(tmem, 256);
    }
#else
    // Portable fallback for the generic compute_103 PTX stage. Never executed
    // on GB300 (the sm_103a cubin takes the tcgen05 path above); correct if
    // ever JIT'd from PTX.
    const int tid = threadIdx.x;
    const int bm = blockIdx.y * 128;
    const int bn = blockIdx.x * BN;
    for (int i = tid; i < 128 * BN; i += 256) {
        const int m = bm + (i / BN);
        const int n = bn + (i % BN);
        float s = 0.f;
        for (int k = 0; k < K; k++) {
            const float a = __bfloat162float(Ah[(size_t)m * K + k]) +
                            __bfloat162float(Al[(size_t)m * K + k]);
            const float b = __bfloat162float(Bh[(size_t)n * K + k]) +
                            __bfloat162float(Bl[(size_t)n * K + k]);
            s += a * b;
        }
        float v = s + lora[(size_t)m * N + n];
        if (mode) {
            v = 0.5f * v * (1.f + erff(v * 0.70710678118654752f));
            const __nv_bfloat16 h = __float2bfloat16(v);
            out_hi[(size_t)m * N + n] = h;
            out_lo[(size_t)m * N + n] = __float2bfloat16(v - __bfloat162float(h));
        }
        out_f32[(size_t)m * N + n] = v;
    }
#endif
}

// ---------------------------------------------------------------------------
// Launch sequence
// ---------------------------------------------------------------------------
extern "C" void kernel_launch(void* const* d_in, const int* in_sizes, int n_in,
                              void* d_out, int out_size)
{
    (void)in_sizes; (void)n_in; (void)out_size;
    const float* x     = (const float*)d_in[0];
    const float* rw    = (const float*)d_in[1];
    const float* rb    = (const float*)d_in[2];
    const float* fc1w  = (const float*)d_in[3];
    const float* fc1b  = (const float*)d_in[4];
    const float* fc2w  = (const float*)d_in[5];
    const float* fc2b  = (const float*)d_in[6];
    const float* A_dn  = (const float*)d_in[7];
    const float* Ab_dn = (const float*)d_in[8];
    const float* B_dn  = (const float*)d_in[9];
    const float* Bb_dn = (const float*)d_in[10];
    const float* A_up  = (const float*)d_in[11];
    const float* Ab_up = (const float*)d_in[12];
    const float* B_up  = (const float*)d_in[13];
    const float* Bb_up = (const float*)d_in[14];

    float* out    = (float*)d_out;
    float* out_up = out;
    float* out_rt = out + (size_t)T_TOK * D_IN;
    float* out_ec = out_rt + (size_t)T_TOK * E_EXP;

    float *abuf_p = nullptr, *lora_p = nullptr;
    __nv_bfloat16 *xhi, *xlo, *w1hi, *w1lo, *w2hi, *w2lo, *ahi, *alo;
    cudaGetSymbolAddress((void**)&abuf_p, g_abuf);
    cudaGetSymbolAddress((void**)&lora_p, g_lora);
    cudaGetSymbolAddress((void**)&xhi,  g_xhi);
    cudaGetSymbolAddress((void**)&xlo,  g_xlo);
    cudaGetSymbolAddress((void**)&w1hi, g_w1hi);
    cudaGetSymbolAddress((void**)&w1lo, g_w1lo);
    cudaGetSymbolAddress((void**)&w2hi, g_w2hi);
    cudaGetSymbolAddress((void**)&w2lo, g_w2lo);
    cudaGetSymbolAddress((void**)&ahi,  g_ahi);
    cudaGetSymbolAddress((void**)&alo,  g_alo);

    cudaFuncSetAttribute(mma_gemm_kernel,
                         cudaFuncAttributeMaxDynamicSharedMemorySize, SMEM_BYTES);

    // hi/lo splits of x and the frozen weights
    const int n4_xd = T_TOK * D_IN / 4;      // == H*D/4 == D*H/4
    cvt_hilo_kernel<<<(n4_xd + 255) / 256, 256>>>(x,    xhi,  xlo,  n4_xd);
    cvt_hilo_kernel<<<(n4_xd + 255) / 256, 256>>>(fc1w, w1hi, w1lo, H_DIM * D_IN / 4);
    cvt_hilo_kernel<<<(n4_xd + 255) / 256, 256>>>(fc2w, w2hi, w2lo, D_IN * H_DIM / 4);

    // router + grouping
    router_kernel<<<T_TOK, 256>>>(x, rw, rb, out_rt, out_ec);
    group_kernel<<<1, 256>>>();

    // ---- down: LoRA staging then fc1 GEMM (tensor cores) + GELU ----
    zero_h_kernel<<<(T_TOK * R_RANK + 255) / 256, 256>>>();
    rank_kernel<<<dim3(MAX_TILES, D_IN / 64), 256>>>(x, D_IN, 64, A_dn, Ab_dn);
    lorab_kernel<<<dim3(MAX_TILES, H_DIM / 128), 256>>>(B_dn, Bb_dn, fc1b, H_DIM, lora_p);
    mma_gemm_kernel<<<dim3(H_DIM / BN, T_TOK / 128), 256, SMEM_BYTES>>>(
        xhi, xlo, w1hi, w1lo, lora_p, H_DIM, D_IN, 1, abuf_p, ahi, alo);

    // ---- up: LoRA staging then fc2 GEMM (tensor cores) ----
    zero_h_kernel<<<(T_TOK * R_RANK + 255) / 256, 256>>>();
    rank_kernel<<<dim3(MAX_TILES, H_DIM / 64), 256>>>(abuf_p, H_DIM, 64, A_up, Ab_up);
    lorab_kernel<<<dim3(MAX_TILES, D_IN / 128), 256>>>(B_up, Bb_up, fc2b, D_IN, lora_p);
    mma_gemm_kernel<<<dim3(D_IN / BN, T_TOK / 128), 256, SMEM_BYTES>>>(
        ahi, alo, w2hi, w2lo, lora_p, D_IN, H_DIM, 0, out_up, nullptr, nullptr);
}